// round 2
// baseline (speedup 1.0000x reference)
#include <cuda_runtime.h>
#include <math.h>

#define Nn 2048
#define Uu 64
#define ALPHA 1.0f

// ---------------- scratch (no allocations allowed) ----------------
__device__ float        g_L[(size_t)Nn * Nn];      // 16 MB: logits, then exp values
__device__ unsigned int g_colmaxk[Nn];             // ordered-key column max
__device__ float        g_colpart[16 * Nn];        // per-i-chunk partial column sums
__device__ float        g_colinv[Nn];              // 1 / column sum
__device__ float        g_head[Nn];
__device__ float        g_oppart[8 * (size_t)Nn * Uu]; // split-K partials (4 MB)
__device__ float        g_rr[Nn];                  // return ratio per row

// monotonic float->uint key (for atomicMax on floats incl. negatives)
__device__ __forceinline__ unsigned fkey(float f) {
    unsigned u = __float_as_uint(f);
    return (u & 0x80000000u) ? ~u : (u | 0x80000000u);
}
__device__ __forceinline__ float funkey(unsigned k) {
    unsigned u = (k & 0x80000000u) ? (k & 0x7FFFFFFFu) : ~k;
    return __uint_as_float(u);
}

// ---------------- K1: init colmax keys + head scores ----------------
__global__ void k_init(const float* __restrict__ feature,
                       const float* __restrict__ head_w,
                       const float* __restrict__ head_b) {
    int i = blockIdx.x * blockDim.x + threadIdx.x;
    if (i >= Nn) return;
    g_colmaxk[i] = fkey(-INFINITY);
    const float4* fr = (const float4*)(feature + (size_t)i * Uu);
    const float4* hw = (const float4*)head_w;
    float acc = 0.f;
#pragma unroll
    for (int k = 0; k < 16; k++) {
        float4 a = fr[k], w = hw[k];
        acc += a.x * w.x + a.y * w.y + a.z * w.z + a.w * w.w;
    }
    g_head[i] = fmaxf(acc + head_b[0], 0.f);
}

// ---------------- K2: the 1 GiB streaming kernel ----------------
// L[i,j] = relu(relation[i,j,:]·rel_w + rel_b) + rel_mask[i,j] + head[i]
__global__ void k_rel(const float* __restrict__ relation,
                      const float* __restrict__ rel_w,
                      const float* __restrict__ rel_b,
                      const float* __restrict__ rel_mask) {
    __shared__ float4 sw[16];
    if (threadIdx.x < 16) sw[threadIdx.x] = ((const float4*)rel_w)[threadIdx.x];
    __syncthreads();
    size_t p = (size_t)blockIdx.x * 256 + threadIdx.x;   // pair index i*N+j
    const float4* rp = (const float4*)relation + p * 16;
    float acc = 0.f;
#pragma unroll
    for (int k = 0; k < 16; k++) {
        float4 a = rp[k], w = sw[k];
        acc += a.x * w.x + a.y * w.y + a.z * w.z + a.w * w.w;
    }
    float v = fmaxf(acc + rel_b[0], 0.f);
    int i = (int)(p >> 11);
    g_L[p] = v + rel_mask[p] + g_head[i];
}

// ---------------- K3a: column max (softmax axis 0) ----------------
__global__ void k_colmax() {
    int j  = blockIdx.x * 256 + threadIdx.x;
    int i0 = blockIdx.y * 128;
    float m = -INFINITY;
    size_t idx = (size_t)i0 * Nn + j;
#pragma unroll 8
    for (int k = 0; k < 128; k++) { m = fmaxf(m, g_L[idx]); idx += Nn; }
    atomicMax(&g_colmaxk[j], fkey(m));
}

// ---------------- K3b: E = exp(L - M), partial column sums ----------------
__global__ void k_expsum() {
    int j  = blockIdx.x * 256 + threadIdx.x;
    int i0 = blockIdx.y * 128;
    float M = funkey(g_colmaxk[j]);
    float s = 0.f;
    size_t idx = (size_t)i0 * Nn + j;
#pragma unroll 4
    for (int k = 0; k < 128; k++) {
        float e = __expf(g_L[idx] - M);
        g_L[idx] = e;
        s += e;
        idx += Nn;
    }
    g_colpart[blockIdx.y * Nn + j] = s;   // deterministic (fixed slot)
}

// ---------------- K3c: reduce partials -> 1/S_j ----------------
__global__ void k_colsum() {
    int j = blockIdx.x * blockDim.x + threadIdx.x;
    if (j >= Nn) return;
    float s = 0.f;
#pragma unroll
    for (int c = 0; c < 16; c++) s += g_colpart[c * Nn + j];
    g_colinv[j] = 1.0f / s;
}

// ---------------- K4: split-K GEMM  op = E @ (feature * colinv) ----------------
// grid (32 row-blocks, 8 j-chunks), 256 threads, BM=64, BU=64, TJ=64, 4x4 reg tiles.
__global__ void k_gemm(const float* __restrict__ feature) {
    __shared__ float Es[64][65];
    __shared__ float fs[64][68];

    const int t  = threadIdx.x;
    const int ug = t & 15;          // u group -> u0 = ug*4
    const int rg = t >> 4;          // row group -> r0 = rg*4
    const int i0 = blockIdx.x * 64;
    const int jc = blockIdx.y;      // j chunk of 256

    float4 acc[4];
#pragma unroll
    for (int r = 0; r < 4; r++) acc[r] = make_float4(0.f, 0.f, 0.f, 0.f);

    for (int tile = 0; tile < 4; tile++) {
        const int j0 = jc * 256 + tile * 64;
        // load E tile: 64 rows x 64 cols, coalesced
#pragma unroll
        for (int k = 0; k < 16; k++) {
            int q = k * 256 + t;
            int r = q >> 6, c = q & 63;
            Es[r][c] = g_L[(size_t)(i0 + r) * Nn + (j0 + c)];
        }
        // load scaled feature tile: fs[jrow][u] = f[j0+jrow][u] * colinv[j0+jrow]
#pragma unroll
        for (int k = 0; k < 16; k++) {
            int q = k * 256 + t;
            int jr = q >> 6, u = q & 63;
            fs[jr][u] = feature[(size_t)(j0 + jr) * Uu + u] * g_colinv[j0 + jr];
        }
        __syncthreads();
#pragma unroll
        for (int jj = 0; jj < 64; jj++) {
            float4 b = *(const float4*)&fs[jj][ug * 4];
            float a0 = Es[rg * 4 + 0][jj];
            float a1 = Es[rg * 4 + 1][jj];
            float a2 = Es[rg * 4 + 2][jj];
            float a3 = Es[rg * 4 + 3][jj];
            acc[0].x += a0 * b.x; acc[0].y += a0 * b.y; acc[0].z += a0 * b.z; acc[0].w += a0 * b.w;
            acc[1].x += a1 * b.x; acc[1].y += a1 * b.y; acc[1].z += a1 * b.z; acc[1].w += a1 * b.w;
            acc[2].x += a2 * b.x; acc[2].y += a2 * b.y; acc[2].z += a2 * b.z; acc[2].w += a2 * b.w;
            acc[3].x += a3 * b.x; acc[3].y += a3 * b.y; acc[3].z += a3 * b.z; acc[3].w += a3 * b.w;
        }
        __syncthreads();
    }
    size_t base = (size_t)jc * Nn * Uu;
#pragma unroll
    for (int r = 0; r < 4; r++) {
        *(float4*)&g_oppart[base + (size_t)(i0 + rg * 4 + r) * Uu + ug * 4] = acc[r];
    }
}

// ---------------- K5: prediction + return ratio per row ----------------
__global__ void k_pred(const float* __restrict__ feature,
                       const float* __restrict__ pred_w,
                       const float* __restrict__ pred_b,
                       const float* __restrict__ base_price) {
    int i = blockIdx.x * blockDim.x + threadIdx.x;
    if (i >= Nn) return;
    float dot = pred_b[0];
    const float4* fr = (const float4*)(feature + (size_t)i * Uu);
    const float4* pw = (const float4*)pred_w;            // first U weights
    const float4* pw2 = (const float4*)(pred_w + Uu);    // second U weights
#pragma unroll
    for (int k = 0; k < 16; k++) {
        float4 a = fr[k], w = pw[k];
        dot += a.x * w.x + a.y * w.y + a.z * w.z + a.w * w.w;
    }
#pragma unroll
    for (int k = 0; k < 16; k++) {
        float4 s = make_float4(0.f, 0.f, 0.f, 0.f);
#pragma unroll
        for (int c = 0; c < 8; c++) {
            float4 v = *(const float4*)&g_oppart[(size_t)c * Nn * Uu + (size_t)i * Uu + k * 4];
            s.x += v.x; s.y += v.y; s.z += v.z; s.w += v.w;
        }
        float4 w = pw2[k];
        dot += s.x * w.x + s.y * w.y + s.z * w.z + s.w * w.w;
    }
    float pred = dot >= 0.f ? dot : 0.2f * dot;          // leaky relu slope 0.2
    float bp = base_price[i];
    g_rr[i] = (pred - bp) / bp;
}

// ---------------- K6: final losses (single block) ----------------
__global__ void k_final(const float* __restrict__ ground_truth,
                        const float* __restrict__ mask,
                        float* __restrict__ out, int out_size) {
    __shared__ float s_reg[256], s_p[256], s_n[256];
    int t = threadIdx.x;
    float reg = 0.f, p = 0.f, ng = 0.f;
    for (int i = t; i < Nn; i += 256) {
        float rr = g_rr[i];
        float d = rr - ground_truth[i];
        reg += d * d;
        float x = rr * mask[i];
        p  += fmaxf(x, 0.f);
        ng += fminf(x, 0.f);
    }
    s_reg[t] = reg; s_p[t] = p; s_n[t] = ng;
    __syncthreads();
    for (int st = 128; st > 0; st >>= 1) {
        if (t < st) {
            s_reg[t] += s_reg[t + st];
            s_p[t]   += s_p[t + st];
            s_n[t]   += s_n[t + st];
        }
        __syncthreads();
    }
    if (t == 0) {
        float regl = s_reg[0];
        float P = s_p[0], Ng = s_n[0];
        // mean over NxN of relu(x_i * x_j) = (P^2 + Ng^2) / N^2  (mask >= 0)
        float rank = (P * P + Ng * Ng) / ((float)Nn * (float)Nn);
        float loss = regl + ALPHA * rank;
        if (out_size >= 1) out[0] = loss;
        if (out_size >= 2) out[1] = regl;
        if (out_size >= 3) out[2] = rank;
    }
}

// ---------------- launch ----------------
extern "C" void kernel_launch(void* const* d_in, const int* in_sizes, int n_in,
                              void* d_out, int out_size) {
    const float* feature      = (const float*)d_in[0];
    const float* relation     = (const float*)d_in[1];
    const float* rel_mask     = (const float*)d_in[2];
    const float* base_price   = (const float*)d_in[3];
    const float* ground_truth = (const float*)d_in[4];
    const float* mask         = (const float*)d_in[5];
    const float* rel_w        = (const float*)d_in[6];
    const float* rel_b        = (const float*)d_in[7];
    const float* head_w       = (const float*)d_in[8];
    const float* head_b       = (const float*)d_in[9];
    // tail_w (10) / tail_b (11) are dead: tail[j] is constant per softmax column (axis 0)
    const float* pred_w       = (const float*)d_in[12];
    const float* pred_b       = (const float*)d_in[13];
    float* out = (float*)d_out;

    k_init<<<(Nn + 255) / 256, 256>>>(feature, head_w, head_b);
    k_rel<<<(Nn * Nn) / 256, 256>>>(relation, rel_w, rel_b, rel_mask);
    {
        dim3 g(Nn / 256, 16);
        k_colmax<<<g, 256>>>();
        k_expsum<<<g, 256>>>();
    }
    k_colsum<<<(Nn + 255) / 256, 256>>>();
    {
        dim3 g(Nn / 64, 8);
        k_gemm<<<g, 256>>>(feature);
    }
    k_pred<<<(Nn + 255) / 256, 256>>>(feature, pred_w, pred_b, base_price);
    k_final<<<1, 256>>>(ground_truth, mask, out, out_size);
}

// round 3
// speedup vs baseline: 1.8035x; 1.8035x over previous
#include <cuda_runtime.h>
#include <math.h>

#define Nn 2048
#define Uu 64
#define ALPHA 1.0f
#define KCH 16            // split-K chunks in the aggregation GEMM

// ---------------- scratch (no allocations allowed) ----------------
__device__ float g_L[(size_t)Nn * Nn];                 // 16 MB: E = exp(logits)
__device__ float g_colpart[64 * Nn];                   // partial column sums
__device__ float g_colinv[Nn];                         // 1 / column sum
__device__ float g_head[Nn];
__device__ float g_oppart[KCH * (size_t)Nn * Uu];      // split-K partials (8 MB)
__device__ float g_rr[Nn];                             // return ratio per row

// ---------------- K1: head scores ----------------
__global__ void k_init(const float* __restrict__ feature,
                       const float* __restrict__ head_w,
                       const float* __restrict__ head_b) {
    int i = blockIdx.x * blockDim.x + threadIdx.x;
    if (i >= Nn) return;
    const float4* fr = (const float4*)(feature + (size_t)i * Uu);
    const float4* hw = (const float4*)head_w;
    float4 a4 = make_float4(0.f, 0.f, 0.f, 0.f);
#pragma unroll
    for (int k = 0; k < 16; k++) {
        float4 a = fr[k], w = hw[k];
        a4.x += a.x * w.x; a4.y += a.y * w.y; a4.z += a.z * w.z; a4.w += a.w * w.w;
    }
    g_head[i] = fmaxf((a4.x + a4.y) + (a4.z + a4.w) + head_b[0], 0.f);
}

// ---------------- K2: 1 GiB stream, fused logit + exp ----------------
// E[i,j] = exp( relu(relation[i,j,:]·rel_w + rel_b) + rel_mask[i,j] + head[i] )
// (softmax max-subtraction skipped: logits bounded ~[−1e9, ~12], exp safe in fp32)
// Block: 128 threads, 128 pairs. Stage tile in smem coalesced, then each
// thread dots its own row (row stride 272 B -> conflict-free LDS.128).
#define RSTRIDE 68   // floats per smem row (64 + 4 pad)
__global__ void k_rel_exp(const float* __restrict__ relation,
                          const float* __restrict__ rel_w,
                          const float* __restrict__ rel_b,
                          const float* __restrict__ rel_mask) {
    __shared__ float s_w[64];
    __shared__ float s_tile[128 * RSTRIDE];   // 34.8 KB

    const int t = threadIdx.x;
    if (t < 16) ((float4*)s_w)[t] = ((const float4*)rel_w)[t];

    const size_t pbase = (size_t)blockIdx.x * 128;    // first pair of this block
    // coalesced flat load: 128 pairs * 16 float4 = 2048 float4, 16 per thread
    const float4* src = (const float4*)relation + pbase * 16;
#pragma unroll
    for (int k = 0; k < 16; k++) {
        int idx = k * 128 + t;                 // flat float4 index in tile
        int row = idx >> 4, col = idx & 15;
        *(float4*)&s_tile[row * RSTRIDE + col * 4] = src[idx];
    }
    __syncthreads();

    // each thread: dot its own pair row with w
    const float* rowp = &s_tile[t * RSTRIDE];
    float4 a4 = make_float4(0.f, 0.f, 0.f, 0.f);
#pragma unroll
    for (int k = 0; k < 16; k++) {
        float4 a = *(const float4*)&rowp[k * 4];
        float4 w = *(const float4*)&s_w[k * 4];
        a4.x += a.x * w.x; a4.y += a.y * w.y; a4.z += a.z * w.z; a4.w += a.w * w.w;
    }
    float acc = (a4.x + a4.y) + (a4.z + a4.w);
    size_t p = pbase + t;
    float logit = fmaxf(acc + rel_b[0], 0.f) + rel_mask[p] + g_head[(int)(p >> 11)];
    g_L[p] = __expf(logit);
}

// ---------------- K3a: partial column sums (row-major coalesced) ----------------
__global__ void k_colpart() {
    int j  = blockIdx.x * 256 + threadIdx.x;
    int i0 = blockIdx.y * 32;
    float s = 0.f;
    size_t idx = (size_t)i0 * Nn + j;
#pragma unroll 8
    for (int k = 0; k < 32; k++) { s += g_L[idx]; idx += Nn; }
    g_colpart[blockIdx.y * Nn + j] = s;
}

// ---------------- K3b: reduce partials -> 1/S_j ----------------
__global__ void k_colfin() {
    int j = blockIdx.x * blockDim.x + threadIdx.x;
    if (j >= Nn) return;
    float s = 0.f;
#pragma unroll
    for (int c = 0; c < 64; c++) s += g_colpart[c * Nn + j];
    g_colinv[j] = 1.0f / s;
}

// ---------------- K4: split-K GEMM  op = E @ (feature * colinv) ----------------
// grid (32 row-blocks, KCH j-chunks of 128), 256 threads, 64x64 block, 4x4 reg tiles
__global__ void k_gemm(const float* __restrict__ feature) {
    __shared__ float Es[64][65];
    __shared__ float fs[64][68];

    const int t  = threadIdx.x;
    const int ug = t & 15;          // u0 = ug*4
    const int rg = t >> 4;          // r0 = rg*4
    const int i0 = blockIdx.x * 64;
    const int jc = blockIdx.y;

    float4 acc[4];
#pragma unroll
    for (int r = 0; r < 4; r++) acc[r] = make_float4(0.f, 0.f, 0.f, 0.f);

#pragma unroll
    for (int tile = 0; tile < 2; tile++) {
        const int j0 = jc * 128 + tile * 64;
#pragma unroll
        for (int k = 0; k < 16; k++) {
            int q = k * 256 + t;
            int r = q >> 6, c = q & 63;
            Es[r][c] = g_L[(size_t)(i0 + r) * Nn + (j0 + c)];
        }
#pragma unroll
        for (int k = 0; k < 16; k++) {
            int q = k * 256 + t;
            int jr = q >> 6, u = q & 63;
            fs[jr][u] = feature[(size_t)(j0 + jr) * Uu + u] * g_colinv[j0 + jr];
        }
        __syncthreads();
#pragma unroll
        for (int jj = 0; jj < 64; jj++) {
            float4 b = *(const float4*)&fs[jj][ug * 4];
            float a0 = Es[rg * 4 + 0][jj];
            float a1 = Es[rg * 4 + 1][jj];
            float a2 = Es[rg * 4 + 2][jj];
            float a3 = Es[rg * 4 + 3][jj];
            acc[0].x += a0 * b.x; acc[0].y += a0 * b.y; acc[0].z += a0 * b.z; acc[0].w += a0 * b.w;
            acc[1].x += a1 * b.x; acc[1].y += a1 * b.y; acc[1].z += a1 * b.z; acc[1].w += a1 * b.w;
            acc[2].x += a2 * b.x; acc[2].y += a2 * b.y; acc[2].z += a2 * b.z; acc[2].w += a2 * b.w;
            acc[3].x += a3 * b.x; acc[3].y += a3 * b.y; acc[3].z += a3 * b.z; acc[3].w += a3 * b.w;
        }
        __syncthreads();
    }
    size_t base = (size_t)jc * Nn * Uu;
#pragma unroll
    for (int r = 0; r < 4; r++) {
        *(float4*)&g_oppart[base + (size_t)(i0 + rg * 4 + r) * Uu + ug * 4] = acc[r];
    }
}

// ---------------- K5: prediction + return ratio ----------------
__global__ void k_pred(const float* __restrict__ feature,
                       const float* __restrict__ pred_w,
                       const float* __restrict__ pred_b,
                       const float* __restrict__ base_price) {
    int i = blockIdx.x * blockDim.x + threadIdx.x;
    if (i >= Nn) return;
    float dot = pred_b[0];
    const float4* fr  = (const float4*)(feature + (size_t)i * Uu);
    const float4* pw  = (const float4*)pred_w;
    const float4* pw2 = (const float4*)(pred_w + Uu);
#pragma unroll
    for (int k = 0; k < 16; k++) {
        float4 a = fr[k], w = pw[k];
        dot += a.x * w.x + a.y * w.y + a.z * w.z + a.w * w.w;
    }
#pragma unroll
    for (int k = 0; k < 16; k++) {
        float4 s = make_float4(0.f, 0.f, 0.f, 0.f);
#pragma unroll
        for (int c = 0; c < KCH; c++) {
            float4 v = *(const float4*)&g_oppart[(size_t)c * Nn * Uu + (size_t)i * Uu + k * 4];
            s.x += v.x; s.y += v.y; s.z += v.z; s.w += v.w;
        }
        float4 w = pw2[k];
        dot += s.x * w.x + s.y * w.y + s.z * w.z + s.w * w.w;
    }
    float pred = dot >= 0.f ? dot : 0.2f * dot;
    float bp = base_price[i];
    g_rr[i] = (pred - bp) / bp;
}

// ---------------- K6: final losses (single block) ----------------
__global__ void k_final(const float* __restrict__ ground_truth,
                        const float* __restrict__ mask,
                        float* __restrict__ out, int out_size) {
    __shared__ float s_reg[256], s_p[256], s_n[256];
    int t = threadIdx.x;
    float reg = 0.f, p = 0.f, ng = 0.f;
    for (int i = t; i < Nn; i += 256) {
        float rr = g_rr[i];
        float d = rr - ground_truth[i];
        reg += d * d;
        float x = rr * mask[i];
        p  += fmaxf(x, 0.f);
        ng += fminf(x, 0.f);
    }
    s_reg[t] = reg; s_p[t] = p; s_n[t] = ng;
    __syncthreads();
    for (int st = 128; st > 0; st >>= 1) {
        if (t < st) {
            s_reg[t] += s_reg[t + st];
            s_p[t]   += s_p[t + st];
            s_n[t]   += s_n[t + st];
        }
        __syncthreads();
    }
    if (t == 0) {
        float regl = s_reg[0];
        float P = s_p[0], Ng = s_n[0];
        float rank = (P * P + Ng * Ng) / ((float)Nn * (float)Nn);
        float loss = regl + ALPHA * rank;
        if (out_size >= 1) out[0] = loss;
        if (out_size >= 2) out[1] = regl;
        if (out_size >= 3) out[2] = rank;
    }
}

// ---------------- launch ----------------
extern "C" void kernel_launch(void* const* d_in, const int* in_sizes, int n_in,
                              void* d_out, int out_size) {
    const float* feature      = (const float*)d_in[0];
    const float* relation     = (const float*)d_in[1];
    const float* rel_mask     = (const float*)d_in[2];
    const float* base_price   = (const float*)d_in[3];
    const float* ground_truth = (const float*)d_in[4];
    const float* mask         = (const float*)d_in[5];
    const float* rel_w        = (const float*)d_in[6];
    const float* rel_b        = (const float*)d_in[7];
    const float* head_w       = (const float*)d_in[8];
    const float* head_b       = (const float*)d_in[9];
    // tail_w/tail_b (10/11) dead: tail[j] constant per softmax column (axis 0)
    const float* pred_w       = (const float*)d_in[12];
    const float* pred_b       = (const float*)d_in[13];
    float* out = (float*)d_out;

    k_init<<<(Nn + 255) / 256, 256>>>(feature, head_w, head_b);
    k_rel_exp<<<(Nn * Nn) / 128, 128>>>(relation, rel_w, rel_b, rel_mask);
    {
        dim3 g(Nn / 256, 64);
        k_colpart<<<g, 256>>>();
    }
    k_colfin<<<(Nn + 255) / 256, 256>>>();
    {
        dim3 g(Nn / 64, KCH);
        k_gemm<<<g, 256>>>(feature);
    }
    k_pred<<<(Nn + 255) / 256, 256>>>(feature, pred_w, pred_b, base_price);
    k_final<<<1, 256>>>(ground_truth, mask, out, out_size);
}